// round 3
// baseline (speedup 1.0000x reference)
#include <cuda_runtime.h>
#include <cuda_fp16.h>
#include <cuda_bf16.h>

// Problem shape (fixed by the dataset)
constexpr int B  = 2;
constexpr int H  = 32;
constexpr int S  = 8192;
constexpr int D  = 128;
constexpr int BH = B * H;          // 64
constexpr int NS = 64;             // split-K chunks
constexpr int C  = S / NS;         // 128 rows per chunk

// Scratch (no cudaMalloc allowed -> device globals)
__device__ int   g_dtype;          // 0 = f16, 1 = bf16, 2 = f32
__device__ float g_m[BH * NS];
__device__ float g_l[BH * NS];
__device__ float g_o[(size_t)BH * NS * D];

// ---------------------------------------------------------------------------
// dtype detection: interpret q (8192 elems, >=16384 bytes) three ways and pick
// the interpretation whose mean|x| is closest to E|N(0,1)| = 0.7979.
// ---------------------------------------------------------------------------
__global__ void nd_detect_kernel(const void* qraw)
{
    const int tid = threadIdx.x;
    const __half*         hq = (const __half*)qraw;
    const __nv_bfloat16*  bq = (const __nv_bfloat16*)qraw;
    const float*          fq = (const float*)qraw;

    float s0 = 0.f, s1 = 0.f, s2 = 0.f;
    for (int i = tid; i < 8192; i += 256) {
        float a = fabsf(__half2float(hq[i]));
        if (!isfinite(a) || a > 1e4f) a = 1e4f;
        s0 += a;
        float b = fabsf(__bfloat162float(bq[i]));
        if (!isfinite(b) || b > 1e4f) b = 1e4f;
        s1 += b;
    }
    // Only the first 16384 bytes are guaranteed to exist -> 4096 floats.
    for (int i = tid; i < 4096; i += 256) {
        float c = fabsf(fq[i]);
        if (!isfinite(c) || c > 1e4f) c = 1e4f;
        s2 += c;
    }

    __shared__ float sh[256];
    float sums[3] = {s0, s1, s2};
    float tot[3];
    for (int j = 0; j < 3; j++) {
        sh[tid] = sums[j];
        __syncthreads();
        for (int off = 128; off; off >>= 1) {
            if (tid < off) sh[tid] += sh[tid + off];
            __syncthreads();
        }
        tot[j] = sh[0];
        __syncthreads();
    }

    if (tid == 0) {
        const float target = 0.7978845608f;
        float e0 = fabsf(tot[0] / 8192.f - target);
        float e1 = fabsf(tot[1] / 8192.f - target);
        float e2 = fabsf(tot[2] / 4096.f - target);
        int best = 0; float be = e0;
        if (e1 < be) { best = 1; be = e1; }
        if (e2 < be) { best = 2; be = e2; }
        g_dtype = best;
    }
}

// ---------------------------------------------------------------------------
// Typed 4-element load -> float4, and scalar store.
// ---------------------------------------------------------------------------
__device__ __forceinline__ float4 ld4(const __half* p) {
    uint2 u = *(const uint2*)p;
    float2 a = __half22float2(*(const half2*)&u.x);
    float2 b = __half22float2(*(const half2*)&u.y);
    return make_float4(a.x, a.y, b.x, b.y);
}
__device__ __forceinline__ float4 ld4(const __nv_bfloat16* p) {
    uint2 u = *(const uint2*)p;
    float2 a = __bfloat1622float2(*(const __nv_bfloat162*)&u.x);
    float2 b = __bfloat1622float2(*(const __nv_bfloat162*)&u.y);
    return make_float4(a.x, a.y, b.x, b.y);
}
__device__ __forceinline__ float4 ld4(const float* p) {
    return *(const float4*)p;
}
__device__ __forceinline__ void st1(__half* p, float v)        { *p = __float2half(v); }
__device__ __forceinline__ void st1(__nv_bfloat16* p, float v) { *p = __float2bfloat16(v); }
__device__ __forceinline__ void st1(float* p, float v)         { *p = v; }

// ---------------------------------------------------------------------------
// Kernel 1: per-chunk partial attention.
// grid = (NS, BH), block = 256 (8 warps). Warp w owns rows [16w,16w+16),
// lane l owns dims [4l, 4l+4).
// ---------------------------------------------------------------------------
template<typename T, int ID>
__global__ __launch_bounds__(256, 4)
void nd_partial_kernel(const T* __restrict__ q,
                       const T* __restrict__ k,
                       const T* __restrict__ v)
{
    if (g_dtype != ID) return;

    const int chunk = blockIdx.x;
    const int bh    = blockIdx.y;
    const int tid   = threadIdx.x;
    const int wid   = tid >> 5;
    const int lane  = tid & 31;

    __shared__ float  sc[C];           // scores -> probabilities
    __shared__ float  red[8];
    __shared__ float4 opart[8][32];
    __shared__ float  s_m;

    // q dims for this lane (tiny, L1-cached; every warp loads the same row)
    const float4 qf = ld4(q + (size_t)bh * D + 4 * lane);

    const size_t base = ((size_t)bh * S + (size_t)chunk * C) * D;
    const T* __restrict__ kg = k + base;
    const T* __restrict__ vg = v + base;

    // ---- Scores ----------------------------------------------------------
    #pragma unroll
    for (int i = 0; i < 16; i++) {
        const int r = wid * 16 + i;
        const float4 kf = ld4(kg + (size_t)r * D + 4 * lane);
        float d = kf.x * qf.x + kf.y * qf.y + kf.z * qf.z + kf.w * qf.w;
        #pragma unroll
        for (int o = 16; o; o >>= 1) d += __shfl_xor_sync(~0u, d, o);
        if (lane == 0) sc[r] = d * 0.08838834764831845f;  // 1/sqrt(128)
    }
    __syncthreads();

    // ---- Chunk max --------------------------------------------------------
    const float sval = (tid < C) ? sc[tid] : -1e30f;
    float mv = sval;
    #pragma unroll
    for (int o = 16; o; o >>= 1) mv = fmaxf(mv, __shfl_xor_sync(~0u, mv, o));
    if (lane == 0) red[wid] = mv;
    __syncthreads();
    if (tid == 0) {
        float mm = red[0];
        #pragma unroll
        for (int i = 1; i < 8; i++) mm = fmaxf(mm, red[i]);
        s_m = mm;
    }
    __syncthreads();
    const float m = s_m;

    // ---- p = exp(s - m), l = sum p ----------------------------------------
    const float p = (tid < C) ? __expf(sval - m) : 0.f;
    if (tid < C) sc[tid] = p;
    float sv = p;
    #pragma unroll
    for (int o = 16; o; o >>= 1) sv += __shfl_xor_sync(~0u, sv, o);
    if (lane == 0) red[wid] = sv;
    __syncthreads();                 // orders sc[] writes before V loop too
    if (tid == 0) {
        float ll = 0.f;
        #pragma unroll
        for (int i = 0; i < 8; i++) ll += red[i];
        g_m[bh * NS + chunk] = m;
        g_l[bh * NS + chunk] = ll;
    }

    // ---- o = sum_r p[r] * v_r ----------------------------------------------
    float4 acc = make_float4(0.f, 0.f, 0.f, 0.f);
    #pragma unroll
    for (int i = 0; i < 16; i++) {
        const int r = wid * 16 + i;
        const float pw = sc[r];
        const float4 vf = ld4(vg + (size_t)r * D + 4 * lane);
        acc.x += pw * vf.x;  acc.y += pw * vf.y;
        acc.z += pw * vf.z;  acc.w += pw * vf.w;
    }
    opart[wid][lane] = acc;
    __syncthreads();

    if (tid < C) {
        float s = 0.f;
        #pragma unroll
        for (int w = 0; w < 8; w++)
            s += ((const float*)&opart[w][0])[tid];
        g_o[((size_t)bh * NS + chunk) * D + tid] = s;
    }
}

// ---------------------------------------------------------------------------
// Kernel 2: cross-chunk online-softmax combine.
// ---------------------------------------------------------------------------
template<typename T, int ID>
__global__ __launch_bounds__(128)
void nd_combine_kernel(T* __restrict__ out)
{
    if (g_dtype != ID) return;

    const int bh  = blockIdx.x;
    const int tid = threadIdx.x;

    __shared__ float sm[NS];
    __shared__ float sl[NS];

    if (tid < NS) {
        sm[tid] = g_m[bh * NS + tid];
        sl[tid] = g_l[bh * NS + tid];
    }
    __syncthreads();

    float M = -1e30f;
    #pragma unroll
    for (int c = 0; c < NS; c++) M = fmaxf(M, sm[c]);

    float L = 0.f, acc = 0.f;
    const float* __restrict__ ob = g_o + ((size_t)bh * NS) * D + tid;
    #pragma unroll 8
    for (int c = 0; c < NS; c++) {
        const float a = __expf(sm[c] - M);
        L   += sl[c] * a;
        acc += ob[(size_t)c * D] * a;
    }
    st1(out + (size_t)bh * D + tid, acc / L);
}

// ---------------------------------------------------------------------------
extern "C" void kernel_launch(void* const* d_in, const int* in_sizes, int n_in,
                              void* d_out, int out_size)
{
    // q is the 8192-element input; the two 64M-element inputs are k then v.
    const void* q = nullptr;
    const void* kv[2] = {nullptr, nullptr};
    int nkv = 0;
    for (int i = 0; i < n_in; i++) {
        if (in_sizes[i] == BH * D) q = d_in[i];
        else if (nkv < 2)          kv[nkv++] = d_in[i];
    }

    nd_detect_kernel<<<1, 256>>>(q);

    dim3 grid1(NS, BH);
    nd_partial_kernel<__half, 0><<<grid1, 256>>>(
        (const __half*)q, (const __half*)kv[0], (const __half*)kv[1]);
    nd_partial_kernel<__nv_bfloat16, 1><<<grid1, 256>>>(
        (const __nv_bfloat16*)q, (const __nv_bfloat16*)kv[0], (const __nv_bfloat16*)kv[1]);
    nd_partial_kernel<float, 2><<<grid1, 256>>>(
        (const float*)q, (const float*)kv[0], (const float*)kv[1]);

    nd_combine_kernel<__half, 0><<<BH, 128>>>((__half*)d_out);
    nd_combine_kernel<__nv_bfloat16, 1><<<BH, 128>>>((__nv_bfloat16*)d_out);
    nd_combine_kernel<float, 2><<<BH, 128>>>((float*)d_out);
}

// round 4
// speedup vs baseline: 1.1980x; 1.1980x over previous
#include <cuda_runtime.h>

// Problem shape (fixed by the dataset; inputs arrive as float32)
constexpr int B  = 2;
constexpr int H  = 32;
constexpr int S  = 8192;
constexpr int D  = 128;
constexpr int BH = B * H;          // 64
constexpr int NS = 64;             // split-K chunks
constexpr int C  = S / NS;         // 128 rows per chunk

// Split-K scratch (no cudaMalloc allowed -> device globals)
__device__ float g_m[BH * NS];
__device__ float g_l[BH * NS];
__device__ float g_o[(size_t)BH * NS * D];

__device__ __forceinline__ float4 ldcs4(const float* p) {
    return __ldcs((const float4*)p);   // streaming: evict-first, no L2 persist
}

// ---------------------------------------------------------------------------
// Kernel 1: per-chunk partial attention.
// grid = (NS, BH), block = 256 (8 warps). Warp w owns rows [16w, 16w+16),
// lane l owns dims [4l, 4l+4). Each CTA streams one 64KB K tile + 64KB V tile.
// ---------------------------------------------------------------------------
__global__ __launch_bounds__(256, 4)
void nd_partial_kernel(const float* __restrict__ q,
                       const float* __restrict__ k,
                       const float* __restrict__ v)
{
    const int chunk = blockIdx.x;
    const int bh    = blockIdx.y;
    const int tid   = threadIdx.x;
    const int wid   = tid >> 5;
    const int lane  = tid & 31;

    __shared__ float  sc[C];           // scores -> probabilities
    __shared__ float  red[8];          // cross-warp reduce
    __shared__ float4 opart[8][32];    // per-warp partial o vectors
    __shared__ float  s_m;

    // q dims for this lane (16 KB total array, L1/L2-resident across CTAs)
    const float4 qf = *(const float4*)(q + (size_t)bh * D + 4 * lane);

    const size_t base = ((size_t)bh * S + (size_t)chunk * C) * D;
    const float* __restrict__ kg = k + base;
    const float* __restrict__ vg = v + base;

    // ---- Scores: s[r] = (q . k_r) * scale ---------------------------------
    #pragma unroll
    for (int i = 0; i < 16; i++) {
        const int r = wid * 16 + i;
        const float4 kf = ldcs4(kg + (size_t)r * D + 4 * lane);
        float d = kf.x * qf.x + kf.y * qf.y + kf.z * qf.z + kf.w * qf.w;
        #pragma unroll
        for (int o = 16; o; o >>= 1) d += __shfl_xor_sync(~0u, d, o);
        if (lane == 0) sc[r] = d * 0.08838834764831845f;  // 1/sqrt(128)
    }
    __syncthreads();

    // ---- Chunk max ----------------------------------------------------------
    const float sval = (tid < C) ? sc[tid] : -1e30f;
    float mv = sval;
    #pragma unroll
    for (int o = 16; o; o >>= 1) mv = fmaxf(mv, __shfl_xor_sync(~0u, mv, o));
    if (lane == 0) red[wid] = mv;
    __syncthreads();
    if (tid == 0) {
        float mm = red[0];
        #pragma unroll
        for (int i = 1; i < 8; i++) mm = fmaxf(mm, red[i]);
        s_m = mm;
    }
    __syncthreads();
    const float m = s_m;

    // ---- p = exp(s - m), l = sum p ------------------------------------------
    const float p = (tid < C) ? __expf(sval - m) : 0.f;
    if (tid < C) sc[tid] = p;
    float sv = p;
    #pragma unroll
    for (int o = 16; o; o >>= 1) sv += __shfl_xor_sync(~0u, sv, o);
    if (lane == 0) red[wid] = sv;
    __syncthreads();                 // also orders sc[] writes before V loop
    if (tid == 0) {
        float ll = 0.f;
        #pragma unroll
        for (int i = 0; i < 8; i++) ll += red[i];
        g_m[bh * NS + chunk] = m;
        g_l[bh * NS + chunk] = ll;
    }

    // ---- o = sum_r p[r] * v_r  (lane owns 4 dims) ----------------------------
    float4 acc = make_float4(0.f, 0.f, 0.f, 0.f);
    #pragma unroll
    for (int i = 0; i < 16; i++) {
        const int r = wid * 16 + i;
        const float pw = sc[r];
        const float4 vf = ldcs4(vg + (size_t)r * D + 4 * lane);
        acc.x += pw * vf.x;  acc.y += pw * vf.y;
        acc.z += pw * vf.z;  acc.w += pw * vf.w;
    }
    opart[wid][lane] = acc;
    __syncthreads();

    if (tid < C) {
        float s = 0.f;
        #pragma unroll
        for (int w = 0; w < 8; w++)
            s += ((const float*)&opart[w][0])[tid];
        g_o[((size_t)bh * NS + chunk) * D + tid] = s;
    }
}

// ---------------------------------------------------------------------------
// Kernel 2: cross-chunk online-softmax combine.
// grid = BH, block = 128 (one thread per output dim).
// ---------------------------------------------------------------------------
__global__ __launch_bounds__(128)
void nd_combine_kernel(float* __restrict__ out)
{
    const int bh  = blockIdx.x;
    const int tid = threadIdx.x;

    __shared__ float sm[NS];
    __shared__ float sl[NS];

    if (tid < NS) {
        sm[tid] = g_m[bh * NS + tid];
        sl[tid] = g_l[bh * NS + tid];
    }
    __syncthreads();

    float M = -1e30f;
    #pragma unroll
    for (int c = 0; c < NS; c++) M = fmaxf(M, sm[c]);

    float L = 0.f, acc = 0.f;
    const float* __restrict__ ob = g_o + ((size_t)bh * NS) * D + tid;
    #pragma unroll 8
    for (int c = 0; c < NS; c++) {
        const float a = __expf(sm[c] - M);
        L   += sl[c] * a;
        acc += ob[(size_t)c * D] * a;
    }
    out[(size_t)bh * D + tid] = acc / L;
}

// ---------------------------------------------------------------------------
extern "C" void kernel_launch(void* const* d_in, const int* in_sizes, int n_in,
                              void* d_out, int out_size)
{
    const float* q = (const float*)d_in[0];
    const float* k = (const float*)d_in[1];
    const float* v = (const float*)d_in[2];
    float* out = (float*)d_out;

    dim3 grid1(NS, BH);
    nd_partial_kernel<<<grid1, 256>>>(q, k, v);
    nd_combine_kernel<<<BH, 128>>>(out);
}

// round 5
// speedup vs baseline: 1.2690x; 1.0592x over previous
#include <cuda_runtime.h>

// Problem shape (fixed by the dataset; inputs arrive as float32)
constexpr int B  = 2;
constexpr int H  = 32;
constexpr int S  = 8192;
constexpr int D  = 128;
constexpr int BH = B * H;          // 64
constexpr int NS = 64;             // split-K chunks
constexpr int C  = S / NS;         // 128 rows per chunk

// Split-K scratch (no cudaMalloc allowed -> device globals)
__device__ float g_m[BH * NS];
__device__ float g_l[BH * NS];
__device__ float g_o[(size_t)BH * NS * D];

__device__ __forceinline__ float4 ldcs4(const float* p) {
    return __ldcs((const float4*)p);   // streaming: evict-first, no L2 persist
}

// ---------------------------------------------------------------------------
// Kernel 1: per-chunk partial attention.  (unchanged — at HBM roofline)
// grid = (NS, BH), block = 256 (8 warps). Warp w owns rows [16w, 16w+16),
// lane l owns dims [4l, 4l+4). Each CTA streams one 64KB K tile + 64KB V tile.
// ---------------------------------------------------------------------------
__global__ __launch_bounds__(256, 4)
void nd_partial_kernel(const float* __restrict__ q,
                       const float* __restrict__ k,
                       const float* __restrict__ v)
{
    const int chunk = blockIdx.x;
    const int bh    = blockIdx.y;
    const int tid   = threadIdx.x;
    const int wid   = tid >> 5;
    const int lane  = tid & 31;

    __shared__ float  sc[C];           // scores -> probabilities
    __shared__ float  red[8];          // cross-warp reduce
    __shared__ float4 opart[8][32];    // per-warp partial o vectors
    __shared__ float  s_m;

    const float4 qf = *(const float4*)(q + (size_t)bh * D + 4 * lane);

    const size_t base = ((size_t)bh * S + (size_t)chunk * C) * D;
    const float* __restrict__ kg = k + base;
    const float* __restrict__ vg = v + base;

    // ---- Scores: s[r] = (q . k_r) * scale ---------------------------------
    #pragma unroll
    for (int i = 0; i < 16; i++) {
        const int r = wid * 16 + i;
        const float4 kf = ldcs4(kg + (size_t)r * D + 4 * lane);
        float d = kf.x * qf.x + kf.y * qf.y + kf.z * qf.z + kf.w * qf.w;
        #pragma unroll
        for (int o = 16; o; o >>= 1) d += __shfl_xor_sync(~0u, d, o);
        if (lane == 0) sc[r] = d * 0.08838834764831845f;  // 1/sqrt(128)
    }
    __syncthreads();

    // ---- Chunk max ----------------------------------------------------------
    const float sval = (tid < C) ? sc[tid] : -1e30f;
    float mv = sval;
    #pragma unroll
    for (int o = 16; o; o >>= 1) mv = fmaxf(mv, __shfl_xor_sync(~0u, mv, o));
    if (lane == 0) red[wid] = mv;
    __syncthreads();
    if (tid == 0) {
        float mm = red[0];
        #pragma unroll
        for (int i = 1; i < 8; i++) mm = fmaxf(mm, red[i]);
        s_m = mm;
    }
    __syncthreads();
    const float m = s_m;

    // ---- p = exp(s - m), l = sum p ------------------------------------------
    const float p = (tid < C) ? __expf(sval - m) : 0.f;
    if (tid < C) sc[tid] = p;
    float sv = p;
    #pragma unroll
    for (int o = 16; o; o >>= 1) sv += __shfl_xor_sync(~0u, sv, o);
    if (lane == 0) red[wid] = sv;
    __syncthreads();                 // also orders sc[] writes before V loop
    if (tid == 0) {
        float ll = 0.f;
        #pragma unroll
        for (int i = 0; i < 8; i++) ll += red[i];
        g_m[bh * NS + chunk] = m;
        g_l[bh * NS + chunk] = ll;
    }

    // ---- o = sum_r p[r] * v_r  (lane owns 4 dims) ----------------------------
    float4 acc = make_float4(0.f, 0.f, 0.f, 0.f);
    #pragma unroll
    for (int i = 0; i < 16; i++) {
        const int r = wid * 16 + i;
        const float pw = sc[r];
        const float4 vf = ldcs4(vg + (size_t)r * D + 4 * lane);
        acc.x += pw * vf.x;  acc.y += pw * vf.y;
        acc.z += pw * vf.z;  acc.w += pw * vf.w;
    }
    opart[wid][lane] = acc;
    __syncthreads();

    if (tid < C) {
        float s = 0.f;
        #pragma unroll
        for (int w = 0; w < 8; w++)
            s += ((const float*)&opart[w][0])[tid];
        g_o[((size_t)bh * NS + chunk) * D + tid] = s;
    }
}

// ---------------------------------------------------------------------------
// Kernel 2: cross-chunk online-softmax combine.
// grid = BH, block = 1024 (8 chunk-groups x 128 dims). Thread (cg, d) sums
// chunks [8cg, 8cg+8) for dim d; tree-combine across cg in shared memory.
// ---------------------------------------------------------------------------
__global__ __launch_bounds__(1024)
void nd_combine_kernel(float* __restrict__ out)
{
    const int bh  = blockIdx.x;
    const int tid = threadIdx.x;
    const int d   = tid & 127;     // output dim
    const int cg  = tid >> 7;      // chunk group 0..7

    __shared__ float sm[NS];
    __shared__ float sML[2];       // [0] = M, [1] = L
    __shared__ float part[8][128];

    if (tid < NS) sm[tid] = g_m[bh * NS + tid];
    if (tid >= 128 && tid < 128 + NS) part[0][tid - 128] = g_l[bh * NS + (tid - 128)];
    __syncthreads();

    // Warp 0: global max M, then L = sum_c l_c * exp(m_c - M)
    if (tid < 32) {
        float mv = fmaxf(sm[tid], sm[tid + 32]);
        #pragma unroll
        for (int o = 16; o; o >>= 1) mv = fmaxf(mv, __shfl_xor_sync(~0u, mv, o));
        const float M = mv;  // uniform across warp after full butterfly
        float lv = part[0][tid]      * __expf(sm[tid]      - M)
                 + part[0][tid + 32] * __expf(sm[tid + 32] - M);
        #pragma unroll
        for (int o = 16; o; o >>= 1) lv += __shfl_xor_sync(~0u, lv, o);
        if (tid == 0) { sML[0] = M; sML[1] = lv; }
    }
    __syncthreads();
    const float M = sML[0];

    // Each thread: 8 coalesced chunk rows for its dim.
    float acc = 0.f;
    const float* __restrict__ ob = g_o + (size_t)bh * NS * D + d;
    #pragma unroll
    for (int j = 0; j < 8; j++) {
        const int c = cg * 8 + j;
        acc += ob[(size_t)c * D] * __expf(sm[c] - M);
    }
    __syncthreads();               // part[0][*] (l values) consumed above
    part[cg][d] = acc;
    __syncthreads();

    if (cg == 0) {
        float s = 0.f;
        #pragma unroll
        for (int j = 0; j < 8; j++) s += part[j][d];
        out[(size_t)bh * D + d] = s / sML[1];
    }
}

// ---------------------------------------------------------------------------
extern "C" void kernel_launch(void* const* d_in, const int* in_sizes, int n_in,
                              void* d_out, int out_size)
{
    const float* q = (const float*)d_in[0];
    const float* k = (const float*)d_in[1];
    const float* v = (const float*)d_in[2];
    float* out = (float*)d_out;

    dim3 grid1(NS, BH);
    nd_partial_kernel<<<grid1, 256>>>(q, k, v);
    nd_combine_kernel<<<BH, 1024>>>(out);
}